// round 4
// baseline (speedup 1.0000x reference)
#include <cuda_runtime.h>
#include <cuda_bf16.h>
#include <cstdint>

// Problem constants
#define B_ 128
#define H_ 512
#define I_ 512
#define SIXH 3072
#define BH (B_ * H_)          // 65536
#define CSZ (B_ * H_ * H_)    // 33554432
#define NSPLIT 8              // split-K factor (K=64 per block)

// ---------------- scratch (no allocs allowed) ----------------
__device__ float g_part[NSPLIT][B_ * SIXH];   // split-K partial gates
__device__ float g_f[BH];
__device__ float g_add[BH];
__device__ float g_o[BH];
__device__ float g_q[BH];
__device__ float g_denom[B_];

// ---------------- Kernel 1: partial gates = x @ W^T (split-K=8) ----------------
// M=128(b), N=3072(gate), K=512. NT gemm, both operands K-major.
// 64x64 tile, BK=16, 128 threads, 4x8 micro-tile, double-buffered smem.
#define GBM 64
#define GBN 64
#define GBK 16
#define NKT 4    // k-tiles per block: 64/16

__global__ __launch_bounds__(128) void gemm_kernel(
    const float* __restrict__ x,      // [128,512]
    const float* __restrict__ W)      // [3072,512]
{
    __shared__ float sA[2][GBK][GBM + 4];  // [buf][k][m]
    __shared__ float sB[2][GBK][GBN + 4];  // [buf][k][n]

    const int bn = blockIdx.x * GBN;
    const int bm = blockIdx.y * GBM;
    const int z  = blockIdx.z;                 // k-split 0..7
    const int k_lo = z * 64;

    const int t  = threadIdx.x;
    // loader: each thread loads 8 contiguous k (2 float4) of one row, for A and B
    const int lm = t >> 1;                     // 0..63
    const int lk = (t & 1) * 8;                // 0 or 8
    // compute: 16 (m) x 8 (n) thread grid, micro-tile 4x8
    const int tm = (t >> 3) * 4;               // 0..60
    const int tn = (t & 7) * 8;                // 0..56

    const float* pA = x + (bm + lm) * I_ + k_lo + lk;
    const float* pB = W + (bn + lm) * I_ + k_lo + lk;

    float4 a0, a1, b0, b1;

    // tile 0 -> regs
    a0 = __ldg((const float4*)(pA));     a1 = __ldg((const float4*)(pA + 4));
    b0 = __ldg((const float4*)(pB));     b1 = __ldg((const float4*)(pB + 4));
    // store tile 0 -> buf0
    sA[0][lk + 0][lm] = a0.x; sA[0][lk + 1][lm] = a0.y; sA[0][lk + 2][lm] = a0.z; sA[0][lk + 3][lm] = a0.w;
    sA[0][lk + 4][lm] = a1.x; sA[0][lk + 5][lm] = a1.y; sA[0][lk + 6][lm] = a1.z; sA[0][lk + 7][lm] = a1.w;
    sB[0][lk + 0][lm] = b0.x; sB[0][lk + 1][lm] = b0.y; sB[0][lk + 2][lm] = b0.z; sB[0][lk + 3][lm] = b0.w;
    sB[0][lk + 4][lm] = b1.x; sB[0][lk + 5][lm] = b1.y; sB[0][lk + 6][lm] = b1.z; sB[0][lk + 7][lm] = b1.w;
    // tile 1 -> regs
    a0 = __ldg((const float4*)(pA + 16)); a1 = __ldg((const float4*)(pA + 20));
    b0 = __ldg((const float4*)(pB + 16)); b1 = __ldg((const float4*)(pB + 20));
    __syncthreads();

    float acc[4][8] = {};

    #pragma unroll
    for (int kt = 0; kt < NKT; kt++) {
        const int cur = kt & 1;
        if (kt < NKT - 1) {
            const int nxt = 1 - cur;
            // store prefetched tile kt+1
            sA[nxt][lk + 0][lm] = a0.x; sA[nxt][lk + 1][lm] = a0.y; sA[nxt][lk + 2][lm] = a0.z; sA[nxt][lk + 3][lm] = a0.w;
            sA[nxt][lk + 4][lm] = a1.x; sA[nxt][lk + 5][lm] = a1.y; sA[nxt][lk + 6][lm] = a1.z; sA[nxt][lk + 7][lm] = a1.w;
            sB[nxt][lk + 0][lm] = b0.x; sB[nxt][lk + 1][lm] = b0.y; sB[nxt][lk + 2][lm] = b0.z; sB[nxt][lk + 3][lm] = b0.w;
            sB[nxt][lk + 4][lm] = b1.x; sB[nxt][lk + 5][lm] = b1.y; sB[nxt][lk + 6][lm] = b1.z; sB[nxt][lk + 7][lm] = b1.w;
            if (kt < NKT - 2) {
                int ko = (kt + 2) * GBK;
                a0 = __ldg((const float4*)(pA + ko)); a1 = __ldg((const float4*)(pA + ko + 4));
                b0 = __ldg((const float4*)(pB + ko)); b1 = __ldg((const float4*)(pB + ko + 4));
            }
        }

        #pragma unroll
        for (int k = 0; k < GBK; k++) {
            float4 av  = *reinterpret_cast<const float4*>(&sA[cur][k][tm]);
            float4 bv0 = *reinterpret_cast<const float4*>(&sB[cur][k][tn]);
            float4 bv1 = *reinterpret_cast<const float4*>(&sB[cur][k][tn + 4]);
            float a[4] = {av.x, av.y, av.z, av.w};
            float b[8] = {bv0.x, bv0.y, bv0.z, bv0.w, bv1.x, bv1.y, bv1.z, bv1.w};
            #pragma unroll
            for (int i = 0; i < 4; i++)
                #pragma unroll
                for (int j = 0; j < 8; j++)
                    acc[i][j] = fmaf(a[i], b[j], acc[i][j]);
        }
        __syncthreads();
    }

    float* out = g_part[z];
    #pragma unroll
    for (int i = 0; i < 4; i++) {
        float4 r0 = make_float4(acc[i][0], acc[i][1], acc[i][2], acc[i][3]);
        float4 r1 = make_float4(acc[i][4], acc[i][5], acc[i][6], acc[i][7]);
        float* row = out + (size_t)(bm + tm + i) * SIXH + bn + tn;
        *reinterpret_cast<float4*>(row)     = r0;
        *reinterpret_cast<float4*>(row + 4) = r1;
    }
}

// ---------------- Kernel 2: gate transforms + n.q reduction (fused) ----------------
// One block per batch b, 512 threads (one per h). gate order: ig,fg,og,q,k,v.
__global__ __launch_bounds__(512) void gate_kernel(
    const float* __restrict__ m_prev,
    const float* __restrict__ n_prev,
    const float* __restrict__ bias,
    float* __restrict__ out_m,
    float* __restrict__ out_n)
{
    const int b = blockIdx.x;
    const int h = threadIdx.x;
    const int base = b * SIXH;

    float g[6];
    #pragma unroll
    for (int gi = 0; gi < 6; gi++) {
        int off = base + gi * H_ + h;
        // pairwise sum of the 8 partials (shallow association for accuracy)
        float s01 = g_part[0][off] + g_part[1][off];
        float s23 = g_part[2][off] + g_part[3][off];
        float s45 = g_part[4][off] + g_part[5][off];
        float s67 = g_part[6][off] + g_part[7][off];
        g[gi] = ((s01 + s23) + (s45 + s67)) + bias[gi * H_ + h];
    }
    float ig = g[0], fg = g[1], og = g[2], qv = g[3], kk = g[4], vv = g[5];

    const int idx = b * H_ + h;
    float mp = m_prev[idx];
    float mt = fmaxf(fg + mp, ig);
    float it = expf(ig - mt);
    float ft = expf(fg + mp - mt);
    float kt = 0.04419417382415922f * kk;   // 1/sqrt(512)
    float nt = ft * n_prev[idx] + it * kt;

    out_m[idx] = mt;
    out_n[idx] = nt;
    g_f[idx]   = ft;
    g_add[idx] = it * vv * kt;
    g_o[idx]   = 1.0f / (1.0f + expf(-og));
    g_q[idx]   = qv;

    // deterministic block reduce of nt*qv over 512 threads
    float s = nt * qv;
    #pragma unroll
    for (int off = 16; off; off >>= 1) s += __shfl_xor_sync(0xffffffffu, s, off);

    __shared__ float red[16];
    int w = threadIdx.x >> 5, lane = threadIdx.x & 31;
    if (lane == 0) red[w] = s;
    __syncthreads();
    if (threadIdx.x == 0) {
        float tsum = 0.f;
        #pragma unroll
        for (int i = 0; i < 16; i++) tsum += red[i];
        g_denom[b] = fmaxf(fabsf(tsum), 1e-6f);
    }
}

// ---------------- Kernel 3: C_t update + readout + h_t ----------------
// One warp per (b,i) row of 512 floats; 8 warps per block; q[b] staged in smem.
// C_prev / out_C are touch-once streams -> evict-first (ldcs/stcs).
__global__ __launch_bounds__(256) void cmain_kernel(
    const float* __restrict__ C_prev,
    float* __restrict__ out_C,
    float* __restrict__ out_h)
{
    __shared__ float sq[H_];
    const int b = blockIdx.x >> 6;            // 64 blocks per batch
    const int row0 = (blockIdx.x & 63) * 8;

    const float* q = g_q + b * H_;
    for (int h = threadIdx.x; h < H_; h += 256) sq[h] = q[h];
    __syncthreads();

    const int w = threadIdx.x >> 5;
    const int lane = threadIdx.x & 31;
    const int i = row0 + w;
    const int bi = b * H_ + i;

    const float f   = g_f[bi];
    const float add = g_add[bi];

    const float4* Cp = reinterpret_cast<const float4*>(C_prev) + (size_t)bi * (H_ / 4);
    float4*       Co = reinterpret_cast<float4*>(out_C)        + (size_t)bi * (H_ / 4);
    const float4* q4 = reinterpret_cast<const float4*>(sq);

    float4 c[4];
    #pragma unroll
    for (int t = 0; t < 4; t++) c[t] = __ldcs(Cp + lane + t * 32);

    float acc = 0.f;
    #pragma unroll
    for (int t = 0; t < 4; t++) {
        int j4 = lane + t * 32;
        float4 r;
        r.x = fmaf(f, c[t].x, add);
        r.y = fmaf(f, c[t].y, add);
        r.z = fmaf(f, c[t].z, add);
        r.w = fmaf(f, c[t].w, add);
        __stcs(Co + j4, r);
        float4 qq = q4[j4];
        acc += r.x * qq.x + r.y * qq.y + r.z * qq.z + r.w * qq.w;
    }

    #pragma unroll
    for (int off = 16; off; off >>= 1) acc += __shfl_xor_sync(0xffffffffu, acc, off);

    if (lane == 0)
        out_h[bi] = g_o[bi] * acc / g_denom[b];
}

// ---------------- launch ----------------
extern "C" void kernel_launch(void* const* d_in, const int* in_sizes, int n_in,
                              void* d_out, int out_size)
{
    const float* x      = (const float*)d_in[0];
    // d_in[1] = h_prev (unused by the reference)
    const float* C_prev = (const float*)d_in[2];
    const float* m_prev = (const float*)d_in[3];
    const float* n_prev = (const float*)d_in[4];
    const float* W      = (const float*)d_in[5];
    const float* bias   = (const float*)d_in[6];

    float* out   = (float*)d_out;
    float* out_h = out;                       // [B,H]
    float* out_C = out + BH;                  // [B,H,H]
    float* out_m = out + BH + CSZ;            // [B,H]
    float* out_n = out + BH + CSZ + BH;       // [B,H]

    dim3 ggrid(SIXH / GBN, B_ / GBM, NSPLIT); // (48, 2, 8) = 768 blocks
    gemm_kernel<<<ggrid, 128>>>(x, W);

    gate_kernel<<<B_, 512>>>(m_prev, n_prev, bias, out_m, out_n);

    cmain_kernel<<<B_ * 64, 256>>>(C_prev, out_C, out_h);
}

// round 8
// speedup vs baseline: 1.1225x; 1.1225x over previous
#include <cuda_runtime.h>
#include <cuda_bf16.h>
#include <cstdint>

// Problem constants
#define B_ 128
#define H_ 512
#define I_ 512
#define SIXH 3072
#define BH (B_ * H_)          // 65536
#define CSZ (B_ * H_ * H_)    // 33554432
#define NSPLIT 6

// ---------------- scratch (no allocs allowed) ----------------
__device__ float g_part[NSPLIT][B_ * SIXH];   // split-K partial gates
__device__ float g_f[BH];
__device__ float g_add[BH];
__device__ float g_o[BH];
__device__ float g_q[BH];
__device__ float g_denom[B_];

// ---------------- Kernel 1: partial gates = x @ W^T (fp32 FFMA, split-K=6) ----
// M=128(b), N=3072(gate), K=512. NT gemm, both operands K-major.
// BM=64 x BN=128 tile, BK=16, 256 threads (8 warps), micro-tile 4x8,
// double-buffered smem, one barrier per k-tile.
#define GBM 64
#define GBN 128
#define GBK 16

__global__ __launch_bounds__(256) void gemm_kernel(
    const float* __restrict__ x,      // [128,512]
    const float* __restrict__ W)      // [3072,512]
{
    __shared__ float sA[2][GBK][GBM + 4];   // 8.7 KB
    __shared__ float sB[2][GBK][GBN + 4];   // 16.9 KB

    const int bn = blockIdx.x * GBN;
    const int bm = blockIdx.y * GBM;
    const int z  = blockIdx.z;                        // 0..5
    // k split: z<4 -> 96 wide, z>=4 -> 64 wide  (4*96 + 2*64 = 512)
    const int k_lo = (z < 4) ? z * 96 : 384 + (z - 4) * 64;
    const int nkt  = (z < 4) ? 6 : 4;                 // k-tiles of 16

    const int t   = threadIdx.x;
    const int wid = t >> 5;
    const int lane = t & 31;
    const int wm = wid >> 2;              // 0..1  (32 rows each)
    const int wn = wid & 3;               // 0..3  (32 cols each)
    const int mt = lane & 7;              // 0..7  -> 4 rows
    const int nt = lane >> 3;             // 0..3  -> 8 cols

    // loader indices: A tile 64x16 -> 1 float4/thread; B tile 128x16 -> 2 float4/thread
    const int lr = t >> 2;                // 0..63
    const int lk = (t & 3) * 4;           // 0,4,8,12

    const float* pA  = x + (size_t)(bm + lr) * I_ + k_lo + lk;
    const float* pB0 = W + (size_t)(bn + lr) * I_ + k_lo + lk;
    const float* pB1 = W + (size_t)(bn + lr + 64) * I_ + k_lo + lk;

    float4 ra, rb0, rb1;

    // prologue: tile0 -> buf0, prefetch tile1 -> regs
    ra  = __ldg((const float4*)pA);
    rb0 = __ldg((const float4*)pB0);
    rb1 = __ldg((const float4*)pB1);
    sA[0][lk + 0][lr] = ra.x;  sA[0][lk + 1][lr] = ra.y;  sA[0][lk + 2][lr] = ra.z;  sA[0][lk + 3][lr] = ra.w;
    sB[0][lk + 0][lr] = rb0.x; sB[0][lk + 1][lr] = rb0.y; sB[0][lk + 2][lr] = rb0.z; sB[0][lk + 3][lr] = rb0.w;
    sB[0][lk + 0][lr + 64] = rb1.x; sB[0][lk + 1][lr + 64] = rb1.y; sB[0][lk + 2][lr + 64] = rb1.z; sB[0][lk + 3][lr + 64] = rb1.w;
    ra  = __ldg((const float4*)(pA  + GBK));
    rb0 = __ldg((const float4*)(pB0 + GBK));
    rb1 = __ldg((const float4*)(pB1 + GBK));
    __syncthreads();

    float acc[4][8] = {};
    const int arow = wm * 32 + mt * 4;
    const int bcol = wn * 32 + nt * 8;

    for (int kt = 0; kt < nkt; kt++) {
        const int cur = kt & 1;
        if (kt < nkt - 1) {
            const int nxt = 1 - cur;
            sA[nxt][lk + 0][lr] = ra.x;  sA[nxt][lk + 1][lr] = ra.y;  sA[nxt][lk + 2][lr] = ra.z;  sA[nxt][lk + 3][lr] = ra.w;
            sB[nxt][lk + 0][lr] = rb0.x; sB[nxt][lk + 1][lr] = rb0.y; sB[nxt][lk + 2][lr] = rb0.z; sB[nxt][lk + 3][lr] = rb0.w;
            sB[nxt][lk + 0][lr + 64] = rb1.x; sB[nxt][lk + 1][lr + 64] = rb1.y; sB[nxt][lk + 2][lr + 64] = rb1.z; sB[nxt][lk + 3][lr + 64] = rb1.w;
            if (kt < nkt - 2) {
                const int ko = (kt + 2) * GBK;
                ra  = __ldg((const float4*)(pA  + ko));
                rb0 = __ldg((const float4*)(pB0 + ko));
                rb1 = __ldg((const float4*)(pB1 + ko));
            }
        }

        #pragma unroll
        for (int k = 0; k < GBK; k++) {
            float4 av  = *reinterpret_cast<const float4*>(&sA[cur][k][arow]);
            float4 bv0 = *reinterpret_cast<const float4*>(&sB[cur][k][bcol]);
            float4 bv1 = *reinterpret_cast<const float4*>(&sB[cur][k][bcol + 4]);
            float a[4] = {av.x, av.y, av.z, av.w};
            float b[8] = {bv0.x, bv0.y, bv0.z, bv0.w, bv1.x, bv1.y, bv1.z, bv1.w};
            #pragma unroll
            for (int i = 0; i < 4; i++)
                #pragma unroll
                for (int j = 0; j < 8; j++)
                    acc[i][j] = fmaf(a[i], b[j], acc[i][j]);
        }
        __syncthreads();
    }

    float* out = g_part[z];
    #pragma unroll
    for (int i = 0; i < 4; i++) {
        float* row = out + (size_t)(bm + arow + i) * SIXH + bn + bcol;
        *reinterpret_cast<float4*>(row)     = make_float4(acc[i][0], acc[i][1], acc[i][2], acc[i][3]);
        *reinterpret_cast<float4*>(row + 4) = make_float4(acc[i][4], acc[i][5], acc[i][6], acc[i][7]);
    }
}

// ---------------- Kernel 2: gate transforms + n.q reduction (fused) ----------------
// One block per batch b, 512 threads (one per h). gate order: ig,fg,og,q,k,v.
__global__ __launch_bounds__(512) void gate_kernel(
    const float* __restrict__ m_prev,
    const float* __restrict__ n_prev,
    const float* __restrict__ bias,
    float* __restrict__ out_m,
    float* __restrict__ out_n)
{
    const int b = blockIdx.x;
    const int h = threadIdx.x;
    const int base = b * SIXH;

    float g[6];
    #pragma unroll
    for (int gi = 0; gi < 6; gi++) {
        int off = base + gi * H_ + h;
        float s01 = g_part[0][off] + g_part[1][off];
        float s23 = g_part[2][off] + g_part[3][off];
        float s45 = g_part[4][off] + g_part[5][off];
        g[gi] = ((s01 + s23) + s45) + bias[gi * H_ + h];
    }
    float ig = g[0], fg = g[1], og = g[2], qv = g[3], kk = g[4], vv = g[5];

    const int idx = b * H_ + h;
    float mp = m_prev[idx];
    float mt = fmaxf(fg + mp, ig);
    float it = expf(ig - mt);
    float ft = expf(fg + mp - mt);
    float kt = 0.04419417382415922f * kk;   // 1/sqrt(512)
    float nt = ft * n_prev[idx] + it * kt;

    out_m[idx] = mt;
    out_n[idx] = nt;
    g_f[idx]   = ft;
    g_add[idx] = it * vv * kt;
    g_o[idx]   = 1.0f / (1.0f + expf(-og));
    g_q[idx]   = qv;

    // deterministic block reduce of nt*qv over 512 threads
    float s = nt * qv;
    #pragma unroll
    for (int off = 16; off; off >>= 1) s += __shfl_xor_sync(0xffffffffu, s, off);

    __shared__ float red[16];
    int w = threadIdx.x >> 5, lane = threadIdx.x & 31;
    if (lane == 0) red[w] = s;
    __syncthreads();
    if (threadIdx.x == 0) {
        float tsum = 0.f;
        #pragma unroll
        for (int i = 0; i < 16; i++) tsum += red[i];
        g_denom[b] = fmaxf(fabsf(tsum), 1e-6f);
    }
}

// ---------------- Kernel 3: C_t update + readout + h_t ----------------
// One warp per (b,i) row of 512 floats; 8 warps per block; q[b] staged in smem.
// C_prev / out_C are touch-once streams -> evict-first (ldcs/stcs).
__global__ __launch_bounds__(256) void cmain_kernel(
    const float* __restrict__ C_prev,
    float* __restrict__ out_C,
    float* __restrict__ out_h)
{
    __shared__ float sq[H_];
    const int b = blockIdx.x >> 6;            // 64 blocks per batch
    const int row0 = (blockIdx.x & 63) * 8;

    const float* q = g_q + b * H_;
    for (int h = threadIdx.x; h < H_; h += 256) sq[h] = q[h];
    __syncthreads();

    const int w = threadIdx.x >> 5;
    const int lane = threadIdx.x & 31;
    const int i = row0 + w;
    const int bi = b * H_ + i;

    const float f   = g_f[bi];
    const float add = g_add[bi];

    const float4* Cp = reinterpret_cast<const float4*>(C_prev) + (size_t)bi * (H_ / 4);
    float4*       Co = reinterpret_cast<float4*>(out_C)        + (size_t)bi * (H_ / 4);
    const float4* q4 = reinterpret_cast<const float4*>(sq);

    float4 c[4];
    #pragma unroll
    for (int t = 0; t < 4; t++) c[t] = __ldcs(Cp + lane + t * 32);

    float acc = 0.f;
    #pragma unroll
    for (int t = 0; t < 4; t++) {
        int j4 = lane + t * 32;
        float4 r;
        r.x = fmaf(f, c[t].x, add);
        r.y = fmaf(f, c[t].y, add);
        r.z = fmaf(f, c[t].z, add);
        r.w = fmaf(f, c[t].w, add);
        __stcs(Co + j4, r);
        float4 qq = q4[j4];
        acc += r.x * qq.x + r.y * qq.y + r.z * qq.z + r.w * qq.w;
    }

    #pragma unroll
    for (int off = 16; off; off >>= 1) acc += __shfl_xor_sync(0xffffffffu, acc, off);

    if (lane == 0)
        out_h[bi] = g_o[bi] * acc / g_denom[b];
}

// ---------------- launch ----------------
extern "C" void kernel_launch(void* const* d_in, const int* in_sizes, int n_in,
                              void* d_out, int out_size)
{
    const float* x      = (const float*)d_in[0];
    // d_in[1] = h_prev (unused by the reference)
    const float* C_prev = (const float*)d_in[2];
    const float* m_prev = (const float*)d_in[3];
    const float* n_prev = (const float*)d_in[4];
    const float* W      = (const float*)d_in[5];
    const float* bias   = (const float*)d_in[6];

    float* out   = (float*)d_out;
    float* out_h = out;                       // [B,H]
    float* out_C = out + BH;                  // [B,H,H]
    float* out_m = out + BH + CSZ;            // [B,H]
    float* out_n = out + BH + CSZ + BH;       // [B,H]

    dim3 ggrid(SIXH / GBN, B_ / GBM, NSPLIT); // (24, 2, 6) = 288 blocks
    gemm_kernel<<<ggrid, 256>>>(x, W);

    gate_kernel<<<B_, 512>>>(m_prev, n_prev, bias, out_m, out_n);

    cmain_kernel<<<B_ * 64, 256>>>(C_prev, out_C, out_h);
}

// round 9
// speedup vs baseline: 1.1277x; 1.0047x over previous
#include <cuda_runtime.h>
#include <cuda_bf16.h>
#include <cstdint>

// Problem constants
#define B_ 128
#define H_ 512
#define I_ 512
#define SIXH 3072
#define BH (B_ * H_)          // 65536
#define CSZ (B_ * H_ * H_)    // 33554432
#define NSPLIT 6

// ---------------- scratch (no allocs allowed) ----------------
__device__ float g_part[NSPLIT][B_ * SIXH];   // split-K partial gates
__device__ float g_f[BH];
__device__ float g_add[BH];
__device__ float g_o[BH];
__device__ float g_q[BH];
__device__ float g_denom[B_];

// ---------------- Kernel 1: partial gates = x @ W^T (fp32 FFMA, split-K=6) ----
// M=128(b)=BM, N=3072(gate), K=512. NT gemm, both operands K-major.
// BM=128 x BN=128 tile, BK=16, 256 threads (8 warps, 2m x 4n warp grid),
// micro-tile 8x8 per thread, double-buffered smem, one barrier per k-tile.
// Grid (24, 6) = 144 blocks = one wave.
#define GBM 128
#define GBN 128
#define GBK 16

__global__ __launch_bounds__(256) void gemm_kernel(
    const float* __restrict__ x,      // [128,512]
    const float* __restrict__ W)      // [3072,512]
{
    __shared__ float sA[2][GBK][GBM + 4];   // 16.9 KB
    __shared__ float sB[2][GBK][GBN + 4];   // 16.9 KB

    const int bn = blockIdx.x * GBN;
    const int z  = blockIdx.y;                        // 0..5
    // k split: z<4 -> 96 wide, z>=4 -> 64 wide  (4*96 + 2*64 = 512)
    const int k_lo = (z < 4) ? z * 96 : 384 + (z - 4) * 64;
    const int nkt  = (z < 4) ? 6 : 4;                 // k-tiles of 16

    const int t    = threadIdx.x;
    const int wid  = t >> 5;
    const int lane = t & 31;
    const int wm = wid >> 2;              // 0..1  (64 rows each)
    const int wn = wid & 3;               // 0..3  (32 cols each)
    const int mt = lane & 7;              // 0..7  -> 8 rows
    const int nt = lane >> 3;             // 0..3  -> 8 cols
    const int arow = wm * 64 + mt * 8;
    const int bcol = wn * 32 + nt * 8;

    // loader indices: tiles are 128x16 -> each thread loads 2 contiguous float4
    const int lr = t >> 1;                // 0..127
    const int lk = (t & 1) * 8;           // 0 or 8

    const float* pA = x + (size_t)lr * I_ + k_lo + lk;
    const float* pB = W + (size_t)(bn + lr) * I_ + k_lo + lk;

    float4 a0, a1, b0, b1;

    // prologue: tile0 -> buf0, prefetch tile1 -> regs
    a0 = __ldg((const float4*)pA);       a1 = __ldg((const float4*)(pA + 4));
    b0 = __ldg((const float4*)pB);       b1 = __ldg((const float4*)(pB + 4));
    sA[0][lk + 0][lr] = a0.x; sA[0][lk + 1][lr] = a0.y; sA[0][lk + 2][lr] = a0.z; sA[0][lk + 3][lr] = a0.w;
    sA[0][lk + 4][lr] = a1.x; sA[0][lk + 5][lr] = a1.y; sA[0][lk + 6][lr] = a1.z; sA[0][lk + 7][lr] = a1.w;
    sB[0][lk + 0][lr] = b0.x; sB[0][lk + 1][lr] = b0.y; sB[0][lk + 2][lr] = b0.z; sB[0][lk + 3][lr] = b0.w;
    sB[0][lk + 4][lr] = b1.x; sB[0][lk + 5][lr] = b1.y; sB[0][lk + 6][lr] = b1.z; sB[0][lk + 7][lr] = b1.w;
    a0 = __ldg((const float4*)(pA + GBK));  a1 = __ldg((const float4*)(pA + GBK + 4));
    b0 = __ldg((const float4*)(pB + GBK));  b1 = __ldg((const float4*)(pB + GBK + 4));
    __syncthreads();

    float acc[8][8] = {};

    for (int kt = 0; kt < nkt; kt++) {
        const int cur = kt & 1;
        if (kt < nkt - 1) {
            const int nxt = 1 - cur;
            sA[nxt][lk + 0][lr] = a0.x; sA[nxt][lk + 1][lr] = a0.y; sA[nxt][lk + 2][lr] = a0.z; sA[nxt][lk + 3][lr] = a0.w;
            sA[nxt][lk + 4][lr] = a1.x; sA[nxt][lk + 5][lr] = a1.y; sA[nxt][lk + 6][lr] = a1.z; sA[nxt][lk + 7][lr] = a1.w;
            sB[nxt][lk + 0][lr] = b0.x; sB[nxt][lk + 1][lr] = b0.y; sB[nxt][lk + 2][lr] = b0.z; sB[nxt][lk + 3][lr] = b0.w;
            sB[nxt][lk + 4][lr] = b1.x; sB[nxt][lk + 5][lr] = b1.y; sB[nxt][lk + 6][lr] = b1.z; sB[nxt][lk + 7][lr] = b1.w;
            if (kt < nkt - 2) {
                const int ko = (kt + 2) * GBK;
                a0 = __ldg((const float4*)(pA + ko));  a1 = __ldg((const float4*)(pA + ko + 4));
                b0 = __ldg((const float4*)(pB + ko));  b1 = __ldg((const float4*)(pB + ko + 4));
            }
        }

        #pragma unroll
        for (int k = 0; k < GBK; k++) {
            float4 av0 = *reinterpret_cast<const float4*>(&sA[cur][k][arow]);
            float4 av1 = *reinterpret_cast<const float4*>(&sA[cur][k][arow + 4]);
            float4 bv0 = *reinterpret_cast<const float4*>(&sB[cur][k][bcol]);
            float4 bv1 = *reinterpret_cast<const float4*>(&sB[cur][k][bcol + 4]);
            float a[8] = {av0.x, av0.y, av0.z, av0.w, av1.x, av1.y, av1.z, av1.w};
            float b[8] = {bv0.x, bv0.y, bv0.z, bv0.w, bv1.x, bv1.y, bv1.z, bv1.w};
            #pragma unroll
            for (int i = 0; i < 8; i++)
                #pragma unroll
                for (int j = 0; j < 8; j++)
                    acc[i][j] = fmaf(a[i], b[j], acc[i][j]);
        }
        __syncthreads();
    }

    float* out = g_part[z];
    #pragma unroll
    for (int i = 0; i < 8; i++) {
        float* row = out + (size_t)(arow + i) * SIXH + bn + bcol;
        *reinterpret_cast<float4*>(row)     = make_float4(acc[i][0], acc[i][1], acc[i][2], acc[i][3]);
        *reinterpret_cast<float4*>(row + 4) = make_float4(acc[i][4], acc[i][5], acc[i][6], acc[i][7]);
    }
}

// ---------------- Kernel 2: gate transforms + n.q reduction (fused) ----------------
// One block per batch b, 512 threads (one per h). gate order: ig,fg,og,q,k,v.
__global__ __launch_bounds__(512) void gate_kernel(
    const float* __restrict__ m_prev,
    const float* __restrict__ n_prev,
    const float* __restrict__ bias,
    float* __restrict__ out_m,
    float* __restrict__ out_n)
{
    const int b = blockIdx.x;
    const int h = threadIdx.x;
    const int base = b * SIXH;

    float g[6];
    #pragma unroll
    for (int gi = 0; gi < 6; gi++) {
        int off = base + gi * H_ + h;
        float s01 = g_part[0][off] + g_part[1][off];
        float s23 = g_part[2][off] + g_part[3][off];
        float s45 = g_part[4][off] + g_part[5][off];
        g[gi] = ((s01 + s23) + s45) + bias[gi * H_ + h];
    }
    float ig = g[0], fg = g[1], og = g[2], qv = g[3], kk = g[4], vv = g[5];

    const int idx = b * H_ + h;
    float mp = m_prev[idx];
    float mt = fmaxf(fg + mp, ig);
    float it = expf(ig - mt);
    float ft = expf(fg + mp - mt);
    float kt = 0.04419417382415922f * kk;   // 1/sqrt(512)
    float nt = ft * n_prev[idx] + it * kt;

    out_m[idx] = mt;
    out_n[idx] = nt;
    g_f[idx]   = ft;
    g_add[idx] = it * vv * kt;
    g_o[idx]   = 1.0f / (1.0f + expf(-og));
    g_q[idx]   = qv;

    // deterministic block reduce of nt*qv over 512 threads
    float s = nt * qv;
    #pragma unroll
    for (int off = 16; off; off >>= 1) s += __shfl_xor_sync(0xffffffffu, s, off);

    __shared__ float red[16];
    int w = threadIdx.x >> 5, lane = threadIdx.x & 31;
    if (lane == 0) red[w] = s;
    __syncthreads();
    if (threadIdx.x == 0) {
        float tsum = 0.f;
        #pragma unroll
        for (int i = 0; i < 16; i++) tsum += red[i];
        g_denom[b] = fmaxf(fabsf(tsum), 1e-6f);
    }
}

// ---------------- Kernel 3: C_t update + readout + h_t ----------------
// One warp per (b,i) row of 512 floats; 8 warps per block; q[b] staged in smem.
// C_prev / out_C are touch-once streams -> evict-first (ldcs/stcs).
__global__ __launch_bounds__(256) void cmain_kernel(
    const float* __restrict__ C_prev,
    float* __restrict__ out_C,
    float* __restrict__ out_h)
{
    __shared__ float sq[H_];
    const int b = blockIdx.x >> 6;            // 64 blocks per batch
    const int row0 = (blockIdx.x & 63) * 8;

    const float* q = g_q + b * H_;
    for (int h = threadIdx.x; h < H_; h += 256) sq[h] = q[h];
    __syncthreads();

    const int w = threadIdx.x >> 5;
    const int lane = threadIdx.x & 31;
    const int i = row0 + w;
    const int bi = b * H_ + i;

    const float f   = g_f[bi];
    const float add = g_add[bi];

    const float4* Cp = reinterpret_cast<const float4*>(C_prev) + (size_t)bi * (H_ / 4);
    float4*       Co = reinterpret_cast<float4*>(out_C)        + (size_t)bi * (H_ / 4);
    const float4* q4 = reinterpret_cast<const float4*>(sq);

    float4 c[4];
    #pragma unroll
    for (int t = 0; t < 4; t++) c[t] = __ldcs(Cp + lane + t * 32);

    float acc = 0.f;
    #pragma unroll
    for (int t = 0; t < 4; t++) {
        int j4 = lane + t * 32;
        float4 r;
        r.x = fmaf(f, c[t].x, add);
        r.y = fmaf(f, c[t].y, add);
        r.z = fmaf(f, c[t].z, add);
        r.w = fmaf(f, c[t].w, add);
        __stcs(Co + j4, r);
        float4 qq = q4[j4];
        acc += r.x * qq.x + r.y * qq.y + r.z * qq.z + r.w * qq.w;
    }

    #pragma unroll
    for (int off = 16; off; off >>= 1) acc += __shfl_xor_sync(0xffffffffu, acc, off);

    if (lane == 0)
        out_h[bi] = g_o[bi] * acc / g_denom[b];
}

// ---------------- launch ----------------
extern "C" void kernel_launch(void* const* d_in, const int* in_sizes, int n_in,
                              void* d_out, int out_size)
{
    const float* x      = (const float*)d_in[0];
    // d_in[1] = h_prev (unused by the reference)
    const float* C_prev = (const float*)d_in[2];
    const float* m_prev = (const float*)d_in[3];
    const float* n_prev = (const float*)d_in[4];
    const float* W      = (const float*)d_in[5];
    const float* bias   = (const float*)d_in[6];

    float* out   = (float*)d_out;
    float* out_h = out;                       // [B,H]
    float* out_C = out + BH;                  // [B,H,H]
    float* out_m = out + BH + CSZ;            // [B,H]
    float* out_n = out + BH + CSZ + BH;       // [B,H]

    dim3 ggrid(SIXH / GBN, NSPLIT);           // (24, 6) = 144 blocks = one wave
    gemm_kernel<<<ggrid, 256>>>(x, W);

    gate_kernel<<<B_, 512>>>(m_prev, n_prev, bias, out_m, out_n);

    cmain_kernel<<<B_ * 64, 256>>>(C_prev, out_C, out_h);
}